// round 7
// baseline (speedup 1.0000x reference)
#include <cuda_runtime.h>
#include <cstdint>

#define UU 200000
#define NN 50000
#define EE 1600000

// Scratch (static __device__ arrays; allocation APIs are forbidden)
__device__ float g_P[(size_t)UU * 64];   // u2e @ W1[:64]
__device__ float g_Q[(size_t)NN * 64];   // u2e[nodes] @ W1[64:] + b1
__device__ float g_ex[EE];               // exp(logit) per edge
// Weights pre-packed in m16n8k8 tf32 B-fragment order.
// word[(nt*32 + lane)*16 + ks*2 + reg]:  W[k = ks*8 + tg + reg*4][n = nt*8 + g]
__device__ uint32_t g_W2f[4096];
__device__ uint32_t g_W1tf[4096];
__device__ uint32_t g_W1bf[4096];

// ================= helpers =================
__device__ __forceinline__ uint32_t f2tf(float x) {
    uint32_t r;
    asm("cvt.rna.tf32.f32 %0, %1;" : "=r"(r) : "f"(x));
    return r;
}

// D(16x8,f32) += A(16x8,tf32,row) x B(8x8,tf32,col)
__device__ __forceinline__ void mma_tf32(float (&c)[4],
    uint32_t a0, uint32_t a1, uint32_t a2, uint32_t a3,
    uint32_t b0, uint32_t b1)
{
    asm volatile(
        "mma.sync.aligned.m16n8k8.row.col.f32.tf32.tf32.f32 "
        "{%0,%1,%2,%3}, {%4,%5,%6,%7}, {%8,%9}, {%0,%1,%2,%3};"
        : "+f"(c[0]), "+f"(c[1]), "+f"(c[2]), "+f"(c[3])
        : "r"(a0), "r"(a1), "r"(a2), "r"(a3), "r"(b0), "r"(b1));
}

// Load per-warp A fragments from pitch-68 tf32 smem tile.
// a[ks][0]:(rb+g, ks*8+tg) a[ks][1]:(rb+g+8, .) a[ks][2]:(rb+g, .+4) a[ks][3]:(rb+g+8, .+4)
__device__ __forceinline__ void load_afrag_tf32(
    const uint32_t* __restrict__ sH, int rb, int g, int tg, uint32_t (&a)[8][4])
{
    const uint32_t* r0 = sH + (rb + g) * 68 + tg;
    const uint32_t* r1 = r0 + 8 * 68;
#pragma unroll
    for (int ks = 0; ks < 8; ks++) {
        a[ks][0] = r0[ks * 8];
        a[ks][1] = r1[ks * 8];
        a[ks][2] = r0[ks * 8 + 4];
        a[ks][3] = r1[ks * 8 + 4];
    }
}

// 8 MMAs for one n-tile (K=64)
__device__ __forceinline__ void mma_ntile_tf32(float (&acc)[4],
    const uint32_t (&a)[8][4], const uint32_t* __restrict__ Bf, int nt, int lane)
{
    const uint4* B = (const uint4*)(Bf + (nt * 32 + lane) * 16);
    uint4 b0 = __ldg(B), b1 = __ldg(B + 1), b2 = __ldg(B + 2), b3 = __ldg(B + 3);
    mma_tf32(acc, a[0][0], a[0][1], a[0][2], a[0][3], b0.x, b0.y);
    mma_tf32(acc, a[1][0], a[1][1], a[1][2], a[1][3], b0.z, b0.w);
    mma_tf32(acc, a[2][0], a[2][1], a[2][2], a[2][3], b1.x, b1.y);
    mma_tf32(acc, a[3][0], a[3][1], a[3][2], a[3][3], b1.z, b1.w);
    mma_tf32(acc, a[4][0], a[4][1], a[4][2], a[4][3], b2.x, b2.y);
    mma_tf32(acc, a[5][0], a[5][1], a[5][2], a[5][3], b2.z, b2.w);
    mma_tf32(acc, a[6][0], a[6][1], a[6][2], a[6][3], b3.x, b3.y);
    mma_tf32(acc, a[7][0], a[7][1], a[7][2], a[7][3], b3.z, b3.w);
}

// ============================================================
// prep_pack: pack a 64x64 k-major weight block into tf32 B-fragment order.
// ============================================================
__global__ void prep_pack(const float* __restrict__ W, uint32_t* __restrict__ dst)
{
    int i = blockIdx.x * blockDim.x + threadIdx.x;
    if (i >= 4096) return;
    int nt = i >> 9, lane = (i >> 4) & 31, idx = i & 15;
    int ks = idx >> 1, reg = idx & 1;
    int g = lane >> 2, tg = lane & 3;
    int n = nt * 8 + g;
    int k = ks * 8 + tg + reg * 4;
    dst[i] = f2tf(__ldg(W + k * 64 + n));
}

// ============================================================
// rowgemm_mma: out[r] = src[gather?gth[r]:r] @ W(64x64) (+ bias)  via tf32 MMA
// 256 threads = 8 warps; 128 rows/block.
// ============================================================
template <bool GATHER, bool BIAS>
__global__ void __launch_bounds__(256) rowgemm_mma(
    const float* __restrict__ src, const int* __restrict__ gth,
    const uint32_t* __restrict__ Bf, const float* __restrict__ bias,
    float* __restrict__ out, int rows)
{
    __shared__ uint32_t sH[128 * 68];

    int tid = threadIdx.x;
    int wid = tid >> 5, lane = tid & 31;
    int g = lane >> 2, tg = lane & 3;
    int r0 = blockIdx.x * 128;

    // load rows, convert to tf32, store pitch-68
    for (int i = tid; i < 1024; i += 256) {
        int r = i >> 3, k8 = i & 7;
        int gr = r0 + r;
        float4 p0 = make_float4(0.f, 0.f, 0.f, 0.f), p1 = p0;
        if (gr < rows) {
            long s = GATHER ? (long)__ldg(gth + gr) : (long)gr;
            const float4* Pr = (const float4*)(src + s * 64) + k8 * 2;
            p0 = __ldg(Pr); p1 = __ldg(Pr + 1);
        }
        uint32_t* d = sH + r * 68 + k8 * 8;
        *(uint4*)d       = make_uint4(f2tf(p0.x), f2tf(p0.y), f2tf(p0.z), f2tf(p0.w));
        *(uint4*)(d + 4) = make_uint4(f2tf(p1.x), f2tf(p1.y), f2tf(p1.z), f2tf(p1.w));
    }
    __syncthreads();

    int rb = wid * 16;
    uint32_t a[8][4];
    load_afrag_tf32(sH, rb, g, tg, a);

#pragma unroll
    for (int nt = 0; nt < 8; nt++) {
        float acc[4] = {0.f, 0.f, 0.f, 0.f};
        mma_ntile_tf32(acc, a, Bf, nt, lane);
        int c0 = nt * 8 + tg * 2;
        float b0 = 0.f, b1 = 0.f;
        if (BIAS) { b0 = __ldg(bias + c0); b1 = __ldg(bias + c0 + 1); }
        int row0 = r0 + rb + g, row1 = row0 + 8;
        if (row0 < rows)
            *(float2*)(out + (size_t)row0 * 64 + c0) = make_float2(acc[0] + b0, acc[1] + b1);
        if (row1 < rows)
            *(float2*)(out + (size_t)row1 * 64 + c0) = make_float2(acc[2] + b0, acc[3] + b1);
    }
}

// ============================================================
// edge_mlp_mma: per 128-edge tile
//   h = relu(P[nb]+Q[sg]) -> tf32 tile in smem (pitch 68)
//   D = h @ W2 via tf32 mma.sync, fp32 accum
//   epilogue: relu(D+b2).w3, 4-lane reduce, exp -> g_ex
// ============================================================
__global__ void __launch_bounds__(256) edge_mlp_mma(
    const int* __restrict__ neigh, const int* __restrict__ seg,
    const float* __restrict__ b2, const float* __restrict__ w3,
    const float* __restrict__ b3)
{
    __shared__ uint32_t sH[128 * 68];
    __shared__ int sIdx[256];

    int tid = threadIdx.x;
    int wid = tid >> 5, lane = tid & 31;
    int g = lane >> 2, tg = lane & 3;
    int e0 = blockIdx.x * 128;

    if (tid < 128) {
        sIdx[tid]       = __ldg(neigh + e0 + tid);
        sIdx[128 + tid] = __ldg(seg   + e0 + tid);
    }
    __syncthreads();

    for (int i = tid; i < 1024; i += 256) {
        int r = i >> 3, k8 = i & 7;
        const float4* Pr = (const float4*)(g_P + (size_t)sIdx[r] * 64) + k8 * 2;
        const float4* Qr = (const float4*)(g_Q + (size_t)sIdx[128 + r] * 64) + k8 * 2;
        float4 p0 = __ldg(Pr), p1 = __ldg(Pr + 1);
        float4 q0 = __ldg(Qr), q1 = __ldg(Qr + 1);
        uint32_t* d = sH + r * 68 + k8 * 8;
        *(uint4*)d = make_uint4(
            f2tf(fmaxf(p0.x + q0.x, 0.f)), f2tf(fmaxf(p0.y + q0.y, 0.f)),
            f2tf(fmaxf(p0.z + q0.z, 0.f)), f2tf(fmaxf(p0.w + q0.w, 0.f)));
        *(uint4*)(d + 4) = make_uint4(
            f2tf(fmaxf(p1.x + q1.x, 0.f)), f2tf(fmaxf(p1.y + q1.y, 0.f)),
            f2tf(fmaxf(p1.z + q1.z, 0.f)), f2tf(fmaxf(p1.w + q1.w, 0.f)));
    }
    __syncthreads();

    int rb = wid * 16;
    uint32_t a[8][4];
    load_afrag_tf32(sH, rb, g, tg, a);

    float s0 = 0.f, s1 = 0.f;
#pragma unroll
    for (int nt = 0; nt < 8; nt++) {
        float acc[4] = {0.f, 0.f, 0.f, 0.f};
        mma_ntile_tf32(acc, a, g_W2f, nt, lane);
        int c0 = nt * 8 + tg * 2, c1 = c0 + 1;
        float bb0 = __ldg(b2 + c0), bb1 = __ldg(b2 + c1);
        float ww0 = __ldg(w3 + c0), ww1 = __ldg(w3 + c1);
        s0 += fmaxf(acc[0] + bb0, 0.f) * ww0 + fmaxf(acc[1] + bb1, 0.f) * ww1;
        s1 += fmaxf(acc[2] + bb0, 0.f) * ww0 + fmaxf(acc[3] + bb1, 0.f) * ww1;
    }
    s0 += __shfl_xor_sync(0xffffffffu, s0, 1);
    s0 += __shfl_xor_sync(0xffffffffu, s0, 2);
    s1 += __shfl_xor_sync(0xffffffffu, s1, 1);
    s1 += __shfl_xor_sync(0xffffffffu, s1, 2);
    if (tg == 0) {
        float b3v = __ldg(b3);
        g_ex[e0 + rb + g]     = expf(s0 + b3v);
        g_ex[e0 + rb + g + 8] = expf(s1 + b3v);
    }
}

// ============================================================
// agg: one warp per node — inline rowptr binary search, softmax denom,
// weighted neighbor sum; half-warp float4 lanes, 4 edges in flight.
// ============================================================
__global__ void __launch_bounds__(256) agg_k(
    const int* __restrict__ nodes, const int* __restrict__ neigh,
    const int* __restrict__ seg, const float* __restrict__ u2e,
    float* __restrict__ out)
{
    int w = (blockIdx.x * 256 + threadIdx.x) >> 5;
    int lane = threadIdx.x & 31;
    if (w >= NN) return;
    int half = lane >> 4, l16 = lane & 15;

    // inline lower_bound: lanes 0-15 search w, lanes 16-31 search w+1
    int target = w + half;
    int lo = 0, hi = EE;
    while (lo < hi) {
        int mid = (lo + hi) >> 1;
        if (__ldg(seg + mid) < target) lo = mid + 1; else hi = mid;
    }
    int s = __shfl_sync(0xffffffffu, lo, 0);
    int t = __shfl_sync(0xffffffffu, lo, 16);

    if (s == t) {  // no neighbors: own embedding
        int u = __ldg(nodes + w);
        if (half == 0) {
            float4 v = __ldg((const float4*)(u2e + (size_t)u * 64) + l16);
            *((float4*)(out + (size_t)w * 64) + l16) = v;
        }
        return;
    }

    float d = 0.f;
    for (int e = s + lane; e < t; e += 32) d += __ldg(g_ex + e);
#pragma unroll
    for (int m = 16; m; m >>= 1) d += __shfl_xor_sync(0xffffffffu, d, m);
    float inv = 1.f / d;

    // 4 edges in flight per half-warp; dual accumulators
    float4 a = make_float4(0.f, 0.f, 0.f, 0.f);
    float4 b = make_float4(0.f, 0.f, 0.f, 0.f);
    int e = s;
    for (; e + 8 <= t; e += 8) {
        int   ea = e + half,     eb = e + 2 + half;
        int   ec = e + 4 + half, ed = e + 6 + half;
        int   na = __ldg(neigh + ea), nb = __ldg(neigh + eb);
        int   nc = __ldg(neigh + ec), nd = __ldg(neigh + ed);
        float wa = __ldg(g_ex + ea), wb = __ldg(g_ex + eb);
        float wc = __ldg(g_ex + ec), wd = __ldg(g_ex + ed);
        float4 va = __ldg((const float4*)(u2e + (size_t)na * 64) + l16);
        float4 vb = __ldg((const float4*)(u2e + (size_t)nb * 64) + l16);
        float4 vc = __ldg((const float4*)(u2e + (size_t)nc * 64) + l16);
        float4 vd = __ldg((const float4*)(u2e + (size_t)nd * 64) + l16);
        a.x = fmaf(wa, va.x, fmaf(wb, vb.x, a.x));
        a.y = fmaf(wa, va.y, fmaf(wb, vb.y, a.y));
        a.z = fmaf(wa, va.z, fmaf(wb, vb.z, a.z));
        a.w = fmaf(wa, va.w, fmaf(wb, vb.w, a.w));
        b.x = fmaf(wc, vc.x, fmaf(wd, vd.x, b.x));
        b.y = fmaf(wc, vc.y, fmaf(wd, vd.y, b.y));
        b.z = fmaf(wc, vc.z, fmaf(wd, vd.z, b.z));
        b.w = fmaf(wc, vc.w, fmaf(wd, vd.w, b.w));
    }
    for (; e < t; e += 2) {
        int ee = e + half;
        if (ee < t) {
            int   n0 = __ldg(neigh + ee);
            float w0 = __ldg(g_ex + ee);
            float4 v = __ldg((const float4*)(u2e + (size_t)n0 * 64) + l16);
            a.x = fmaf(w0, v.x, a.x); a.y = fmaf(w0, v.y, a.y);
            a.z = fmaf(w0, v.z, a.z); a.w = fmaf(w0, v.w, a.w);
        }
    }
    a.x += b.x; a.y += b.y; a.z += b.z; a.w += b.w;
    a.x += __shfl_xor_sync(0xffffffffu, a.x, 16);
    a.y += __shfl_xor_sync(0xffffffffu, a.y, 16);
    a.z += __shfl_xor_sync(0xffffffffu, a.z, 16);
    a.w += __shfl_xor_sync(0xffffffffu, a.w, 16);
    if (half == 0) {
        a.x *= inv; a.y *= inv; a.z *= inv; a.w *= inv;
        *((float4*)(out + (size_t)w * 64) + l16) = a;
    }
}

// ============================================================
extern "C" void kernel_launch(void* const* d_in, const int* in_sizes, int n_in,
                              void* d_out, int out_size)
{
    const int*   nodes = (const int*)d_in[0];
    const int*   neigh = (const int*)d_in[1];
    const int*   seg   = (const int*)d_in[2];
    const float* u2e   = (const float*)d_in[3];
    const float* W1    = (const float*)d_in[4];
    const float* b1    = (const float*)d_in[5];
    const float* W2    = (const float*)d_in[6];
    const float* b2    = (const float*)d_in[7];
    const float* w3    = (const float*)d_in[8];
    const float* b3    = (const float*)d_in[9];
    float* out = (float*)d_out;

    float *dP, *dQ;
    cudaGetSymbolAddress((void**)&dP, g_P);
    cudaGetSymbolAddress((void**)&dQ, g_Q);
    uint32_t *pW2, *pW1t, *pW1b;
    cudaGetSymbolAddress((void**)&pW2,  g_W2f);
    cudaGetSymbolAddress((void**)&pW1t, g_W1tf);
    cudaGetSymbolAddress((void**)&pW1b, g_W1bf);

    // weight packs (tf32 fragment order)
    prep_pack<<<16, 256>>>(W2, pW2);
    prep_pack<<<16, 256>>>(W1, pW1t);
    prep_pack<<<16, 256>>>(W1 + 64 * 64, pW1b);
    // P = u2e @ W1[:64]
    rowgemm_mma<false, false><<<(UU + 127) / 128, 256>>>(
        u2e, nullptr, pW1t, nullptr, dP, UU);
    // Q = u2e[nodes] @ W1[64:] + b1
    rowgemm_mma<true, true><<<(NN + 127) / 128, 256>>>(
        u2e, nodes, pW1b, b1, dQ, NN);
    // per-edge MLP -> exp(logit)  (tf32 MMA)
    edge_mlp_mma<<<EE / 128, 256>>>(neigh, seg, b2, w3, b3);
    // segment softmax + weighted aggregation (+ zero-neighbor fallback)
    agg_k<<<(NN * 32 + 255) / 256, 256>>>(nodes, neigh, seg, u2e, out);
}

// round 8
// speedup vs baseline: 1.5670x; 1.5670x over previous
#include <cuda_runtime.h>
#include <cuda_bf16.h>
#include <cstdint>

#define UU 200000
#define NN 50000
#define EE 1600000

// Scratch (static __device__ arrays; allocation APIs are forbidden)
__device__ float g_P[(size_t)UU * 64];   // u2e @ W1[:64]
__device__ float g_Q[(size_t)NN * 64];   // u2e[nodes] @ W1[64:] + b1
__device__ float g_ex[EE];               // exp(logit) per edge
// Weights (bf16 hi only) pre-packed in m16n8k16 B-fragment order.
// word[(nt*32 + lane)*8 + ks*2 + reg] (reg0: k=ks*16+tg*2, reg1: +8)
__device__ uint32_t g_W2f[2048];
__device__ uint32_t g_W1tf[2048];  // W1 rows 0..63
__device__ uint32_t g_W1bf[2048];  // W1 rows 64..127

// ================= helpers =================
__device__ __forceinline__ unsigned short f2bf(float x) {
    __nv_bfloat16 b = __float2bfloat16_rn(x);
    return *reinterpret_cast<unsigned short*>(&b);
}
// split pair (a,b) into packed bf16 hi word + residual lo word (elem0 in low half)
__device__ __forceinline__ void split2(float a, float b, uint32_t& hi, uint32_t& lo) {
    asm("cvt.rn.bf16x2.f32 %0, %1, %2;" : "=r"(hi) : "f"(b), "f"(a));
    float ra = a - __uint_as_float(hi << 16);
    float rb = b - __uint_as_float(hi & 0xffff0000u);
    asm("cvt.rn.bf16x2.f32 %0, %1, %2;" : "=r"(lo) : "f"(rb), "f"(ra));
}

// D(16x8,f32) += A(16x16,bf16,row) x B(16x8,bf16,col)
__device__ __forceinline__ void mma_bf16(float (&c)[4],
    uint32_t a0, uint32_t a1, uint32_t a2, uint32_t a3,
    uint32_t b0, uint32_t b1)
{
    asm volatile(
        "mma.sync.aligned.m16n8k16.row.col.f32.bf16.bf16.f32 "
        "{%0,%1,%2,%3}, {%4,%5,%6,%7}, {%8,%9}, {%0,%1,%2,%3};"
        : "+f"(c[0]), "+f"(c[1]), "+f"(c[2]), "+f"(c[3])
        : "r"(a0), "r"(a1), "r"(a2), "r"(a3), "r"(b0), "r"(b1));
}

// 8 MMAs for one n-tile: (Ah + Al) x Bh  == A x round_bf16(B) exactly
__device__ __forceinline__ void mma_2p_ntile(float (&acc)[4],
    const uint32_t (&ahi)[4][4], const uint32_t (&alo)[4][4],
    const uint32_t* __restrict__ Bhi, int nt, int lane)
{
    const uint4* Bh = (const uint4*)(Bhi + (nt * 32 + lane) * 8);
    uint4 bh0 = __ldg(Bh), bh1 = __ldg(Bh + 1);
    mma_bf16(acc, ahi[0][0], ahi[0][1], ahi[0][2], ahi[0][3], bh0.x, bh0.y);
    mma_bf16(acc, alo[0][0], alo[0][1], alo[0][2], alo[0][3], bh0.x, bh0.y);
    mma_bf16(acc, ahi[1][0], ahi[1][1], ahi[1][2], ahi[1][3], bh0.z, bh0.w);
    mma_bf16(acc, alo[1][0], alo[1][1], alo[1][2], alo[1][3], bh0.z, bh0.w);
    mma_bf16(acc, ahi[2][0], ahi[2][1], ahi[2][2], ahi[2][3], bh1.x, bh1.y);
    mma_bf16(acc, alo[2][0], alo[2][1], alo[2][2], alo[2][3], bh1.x, bh1.y);
    mma_bf16(acc, ahi[3][0], ahi[3][1], ahi[3][2], ahi[3][3], bh1.z, bh1.w);
    mma_bf16(acc, alo[3][0], alo[3][1], alo[3][2], alo[3][3], bh1.z, bh1.w);
}

// Load per-warp A fragments from pitch-36 smem tiles
__device__ __forceinline__ void load_afrag(
    const uint32_t* __restrict__ sHhi, const uint32_t* __restrict__ sHlo,
    int rb, int g, int tg, uint32_t (&ahi)[4][4], uint32_t (&alo)[4][4])
{
#pragma unroll
    for (int ks = 0; ks < 4; ks++) {
        int b0 = (rb + g) * 36 + ks * 8 + tg;
        int b1 = b0 + 8 * 36;
        ahi[ks][0] = sHhi[b0];     ahi[ks][1] = sHhi[b1];
        ahi[ks][2] = sHhi[b0 + 4]; ahi[ks][3] = sHhi[b1 + 4];
        alo[ks][0] = sHlo[b0];     alo[ks][1] = sHlo[b1];
        alo[ks][2] = sHlo[b0 + 4]; alo[ks][3] = sHlo[b1 + 4];
    }
}

// ============================================================
// prep_pack: pack a 64x64 k-major weight block into bf16 B-fragment order (hi only).
// ============================================================
__global__ void prep_pack(const float* __restrict__ W, uint32_t* __restrict__ dst)
{
    int i = blockIdx.x * blockDim.x + threadIdx.x;
    if (i >= 2048) return;
    int nt = i >> 8, L = (i >> 3) & 31, w = i & 7;
    int ks = w >> 1, reg = w & 1;
    int g = L >> 2, tg = L & 3;
    int n = nt * 8 + g;
    int k = ks * 16 + reg * 8 + tg * 2;
    float v0 = __ldg(W + k * 64 + n);
    float v1 = __ldg(W + (k + 1) * 64 + n);
    dst[i] = (uint32_t)f2bf(v0) | ((uint32_t)f2bf(v1) << 16);
}

// ============================================================
// rowgemm_mma: out[r] = src[gather?gth[r]:r] @ W(64x64) (+ bias)  via HMMA
// 256 threads = 8 warps; 128 rows/block.
// ============================================================
template <bool GATHER, bool BIAS>
__global__ void __launch_bounds__(256) rowgemm_mma(
    const float* __restrict__ src, const int* __restrict__ gth,
    const uint32_t* __restrict__ Bf, const float* __restrict__ bias,
    float* __restrict__ out, int rows)
{
    __shared__ uint32_t sHhi[128 * 36];
    __shared__ uint32_t sHlo[128 * 36];

    int tid = threadIdx.x;
    int wid = tid >> 5, lane = tid & 31;
    int g = lane >> 2, tg = lane & 3;
    int r0 = blockIdx.x * 128;

    // load + hi/lo split; each iter covers one row's 8-k chunk
    for (int i = tid; i < 1024; i += 256) {
        int r = i >> 3, k8 = i & 7;
        int gr = r0 + r;
        float4 p0 = make_float4(0.f, 0.f, 0.f, 0.f), p1 = p0;
        if (gr < rows) {
            long s = GATHER ? (long)__ldg(gth + gr) : (long)gr;
            const float4* Pr = (const float4*)(src + s * 64) + k8 * 2;
            p0 = __ldg(Pr); p1 = __ldg(Pr + 1);
        }
        uint32_t hi[4], lo[4];
        split2(p0.x, p0.y, hi[0], lo[0]);
        split2(p0.z, p0.w, hi[1], lo[1]);
        split2(p1.x, p1.y, hi[2], lo[2]);
        split2(p1.z, p1.w, hi[3], lo[3]);
        int base = r * 36 + k8 * 4;
        *(uint4*)(sHhi + base) = make_uint4(hi[0], hi[1], hi[2], hi[3]);
        *(uint4*)(sHlo + base) = make_uint4(lo[0], lo[1], lo[2], lo[3]);
    }
    __syncthreads();

    int rb = wid * 16;
    uint32_t ahi[4][4], alo[4][4];
    load_afrag(sHhi, sHlo, rb, g, tg, ahi, alo);

#pragma unroll
    for (int nt = 0; nt < 8; nt++) {
        float acc[4] = {0.f, 0.f, 0.f, 0.f};
        mma_2p_ntile(acc, ahi, alo, Bf, nt, lane);
        int c0 = nt * 8 + tg * 2;
        float a0 = 0.f, a1 = 0.f;
        if (BIAS) { a0 = __ldg(bias + c0); a1 = __ldg(bias + c0 + 1); }
        int row0 = r0 + rb + g, row1 = row0 + 8;
        if (row0 < rows)
            *(float2*)(out + (size_t)row0 * 64 + c0) = make_float2(acc[0] + a0, acc[1] + a1);
        if (row1 < rows)
            *(float2*)(out + (size_t)row1 * 64 + c0) = make_float2(acc[2] + a0, acc[3] + a1);
    }
}

// ============================================================
// edge_mlp_mma: per 128-edge tile
//   h = relu(P[nb]+Q[sg]) -> bf16 hi/lo tiles in smem (pitch 36 words/row)
//   D = (Ah+Al) x W2h via mma.sync (HMMA), fp32 accum
//   epilogue: relu(D+b2).w3, 4-lane reduce, exp -> g_ex
// ============================================================
__global__ void __launch_bounds__(256) edge_mlp_mma(
    const int* __restrict__ neigh, const int* __restrict__ seg,
    const float* __restrict__ b2, const float* __restrict__ w3,
    const float* __restrict__ b3)
{
    __shared__ uint32_t sHhi[128 * 36];
    __shared__ uint32_t sHlo[128 * 36];
    __shared__ int sIdx[256];

    int tid = threadIdx.x;
    int wid = tid >> 5, lane = tid & 31;
    int g = lane >> 2, tg = lane & 3;
    int e0 = blockIdx.x * 128;

    if (tid < 128) {
        sIdx[tid]       = __ldg(neigh + e0 + tid);
        sIdx[128 + tid] = __ldg(seg   + e0 + tid);
    }
    __syncthreads();

    for (int i = tid; i < 1024; i += 256) {
        int r = i >> 3, k8 = i & 7;
        const float4* Pr = (const float4*)(g_P + (size_t)sIdx[r] * 64) + k8 * 2;
        const float4* Qr = (const float4*)(g_Q + (size_t)sIdx[128 + r] * 64) + k8 * 2;
        float4 p0 = __ldg(Pr), p1 = __ldg(Pr + 1);
        float4 q0 = __ldg(Qr), q1 = __ldg(Qr + 1);
        uint32_t hi[4], lo[4];
        split2(fmaxf(p0.x + q0.x, 0.f), fmaxf(p0.y + q0.y, 0.f), hi[0], lo[0]);
        split2(fmaxf(p0.z + q0.z, 0.f), fmaxf(p0.w + q0.w, 0.f), hi[1], lo[1]);
        split2(fmaxf(p1.x + q1.x, 0.f), fmaxf(p1.y + q1.y, 0.f), hi[2], lo[2]);
        split2(fmaxf(p1.z + q1.z, 0.f), fmaxf(p1.w + q1.w, 0.f), hi[3], lo[3]);
        int base = r * 36 + k8 * 4;
        *(uint4*)(sHhi + base) = make_uint4(hi[0], hi[1], hi[2], hi[3]);
        *(uint4*)(sHlo + base) = make_uint4(lo[0], lo[1], lo[2], lo[3]);
    }
    __syncthreads();

    int rb = wid * 16;
    uint32_t ahi[4][4], alo[4][4];
    load_afrag(sHhi, sHlo, rb, g, tg, ahi, alo);

    float s0 = 0.f, s1 = 0.f;
#pragma unroll
    for (int nt = 0; nt < 8; nt++) {
        float acc[4] = {0.f, 0.f, 0.f, 0.f};
        mma_2p_ntile(acc, ahi, alo, g_W2f, nt, lane);
        int c0 = nt * 8 + tg * 2, c1 = c0 + 1;
        float bb0 = __ldg(b2 + c0), bb1 = __ldg(b2 + c1);
        float ww0 = __ldg(w3 + c0), ww1 = __ldg(w3 + c1);
        s0 += fmaxf(acc[0] + bb0, 0.f) * ww0 + fmaxf(acc[1] + bb1, 0.f) * ww1;
        s1 += fmaxf(acc[2] + bb0, 0.f) * ww0 + fmaxf(acc[3] + bb1, 0.f) * ww1;
    }
    s0 += __shfl_xor_sync(0xffffffffu, s0, 1);
    s0 += __shfl_xor_sync(0xffffffffu, s0, 2);
    s1 += __shfl_xor_sync(0xffffffffu, s1, 1);
    s1 += __shfl_xor_sync(0xffffffffu, s1, 2);
    if (tg == 0) {
        float b3v = __ldg(b3);
        g_ex[e0 + rb + g]     = expf(s0 + b3v);
        g_ex[e0 + rb + g + 8] = expf(s1 + b3v);
    }
}

// ============================================================
// agg: one warp per node — inline rowptr binary search, softmax denom,
// weighted neighbor sum; half-warp float4 lanes, 4 edges in flight.
// ============================================================
__global__ void __launch_bounds__(256) agg_k(
    const int* __restrict__ nodes, const int* __restrict__ neigh,
    const int* __restrict__ seg, const float* __restrict__ u2e,
    float* __restrict__ out)
{
    int w = (blockIdx.x * 256 + threadIdx.x) >> 5;
    int lane = threadIdx.x & 31;
    if (w >= NN) return;
    int half = lane >> 4, l16 = lane & 15;

    // inline lower_bound: lanes 0-15 search w, lanes 16-31 search w+1
    int target = w + half;
    int lo = 0, hi = EE;
    while (lo < hi) {
        int mid = (lo + hi) >> 1;
        if (__ldg(seg + mid) < target) lo = mid + 1; else hi = mid;
    }
    int s = __shfl_sync(0xffffffffu, lo, 0);
    int t = __shfl_sync(0xffffffffu, lo, 16);

    if (s == t) {  // no neighbors: own embedding
        int u = __ldg(nodes + w);
        if (half == 0) {
            float4 v = __ldg((const float4*)(u2e + (size_t)u * 64) + l16);
            *((float4*)(out + (size_t)w * 64) + l16) = v;
        }
        return;
    }

    float d = 0.f;
    for (int e = s + lane; e < t; e += 32) d += __ldg(g_ex + e);
#pragma unroll
    for (int m = 16; m; m >>= 1) d += __shfl_xor_sync(0xffffffffu, d, m);
    float inv = 1.f / d;

    // 4 edges in flight per half-warp; dual accumulators
    float4 a = make_float4(0.f, 0.f, 0.f, 0.f);
    float4 b = make_float4(0.f, 0.f, 0.f, 0.f);
    int e = s;
    for (; e + 8 <= t; e += 8) {
        int   ea = e + half,     eb = e + 2 + half;
        int   ec = e + 4 + half, ed = e + 6 + half;
        int   na = __ldg(neigh + ea), nb = __ldg(neigh + eb);
        int   nc = __ldg(neigh + ec), nd = __ldg(neigh + ed);
        float wa = __ldg(g_ex + ea), wb = __ldg(g_ex + eb);
        float wc = __ldg(g_ex + ec), wd = __ldg(g_ex + ed);
        float4 va = __ldg((const float4*)(u2e + (size_t)na * 64) + l16);
        float4 vb = __ldg((const float4*)(u2e + (size_t)nb * 64) + l16);
        float4 vc = __ldg((const float4*)(u2e + (size_t)nc * 64) + l16);
        float4 vd = __ldg((const float4*)(u2e + (size_t)nd * 64) + l16);
        a.x = fmaf(wa, va.x, fmaf(wb, vb.x, a.x));
        a.y = fmaf(wa, va.y, fmaf(wb, vb.y, a.y));
        a.z = fmaf(wa, va.z, fmaf(wb, vb.z, a.z));
        a.w = fmaf(wa, va.w, fmaf(wb, vb.w, a.w));
        b.x = fmaf(wc, vc.x, fmaf(wd, vd.x, b.x));
        b.y = fmaf(wc, vc.y, fmaf(wd, vd.y, b.y));
        b.z = fmaf(wc, vc.z, fmaf(wd, vd.z, b.z));
        b.w = fmaf(wc, vc.w, fmaf(wd, vd.w, b.w));
    }
    for (; e < t; e += 2) {
        int ee = e + half;
        if (ee < t) {
            int   n0 = __ldg(neigh + ee);
            float w0 = __ldg(g_ex + ee);
            float4 v = __ldg((const float4*)(u2e + (size_t)n0 * 64) + l16);
            a.x = fmaf(w0, v.x, a.x); a.y = fmaf(w0, v.y, a.y);
            a.z = fmaf(w0, v.z, a.z); a.w = fmaf(w0, v.w, a.w);
        }
    }
    a.x += b.x; a.y += b.y; a.z += b.z; a.w += b.w;
    a.x += __shfl_xor_sync(0xffffffffu, a.x, 16);
    a.y += __shfl_xor_sync(0xffffffffu, a.y, 16);
    a.z += __shfl_xor_sync(0xffffffffu, a.z, 16);
    a.w += __shfl_xor_sync(0xffffffffu, a.w, 16);
    if (half == 0) {
        a.x *= inv; a.y *= inv; a.z *= inv; a.w *= inv;
        *((float4*)(out + (size_t)w * 64) + l16) = a;
    }
}

// ============================================================
extern "C" void kernel_launch(void* const* d_in, const int* in_sizes, int n_in,
                              void* d_out, int out_size)
{
    const int*   nodes = (const int*)d_in[0];
    const int*   neigh = (const int*)d_in[1];
    const int*   seg   = (const int*)d_in[2];
    const float* u2e   = (const float*)d_in[3];
    const float* W1    = (const float*)d_in[4];
    const float* b1    = (const float*)d_in[5];
    const float* W2    = (const float*)d_in[6];
    const float* b2    = (const float*)d_in[7];
    const float* w3    = (const float*)d_in[8];
    const float* b3    = (const float*)d_in[9];
    float* out = (float*)d_out;

    float *dP, *dQ;
    cudaGetSymbolAddress((void**)&dP, g_P);
    cudaGetSymbolAddress((void**)&dQ, g_Q);
    uint32_t *pW2, *pW1t, *pW1b;
    cudaGetSymbolAddress((void**)&pW2,  g_W2f);
    cudaGetSymbolAddress((void**)&pW1t, g_W1tf);
    cudaGetSymbolAddress((void**)&pW1b, g_W1bf);

    // weight packs (bf16 hi, fragment order)
    prep_pack<<<8, 256>>>(W2, pW2);
    prep_pack<<<8, 256>>>(W1, pW1t);
    prep_pack<<<8, 256>>>(W1 + 64 * 64, pW1b);
    // P = u2e @ W1[:64]
    rowgemm_mma<false, false><<<(UU + 127) / 128, 256>>>(
        u2e, nullptr, pW1t, nullptr, dP, UU);
    // Q = u2e[nodes] @ W1[64:] + b1
    rowgemm_mma<true, true><<<(NN + 127) / 128, 256>>>(
        u2e, nodes, pW1b, b1, dQ, NN);
    // per-edge MLP -> exp(logit)  (HMMA)
    edge_mlp_mma<<<EE / 128, 256>>>(neigh, seg, b2, w3, b3);
    // segment softmax + weighted aggregation (+ zero-neighbor fallback)
    agg_k<<<(NN * 32 + 255) / 256, 256>>>(nodes, neigh, seg, u2e, out);
}

// round 9
// speedup vs baseline: 1.6660x; 1.0632x over previous
#include <cuda_runtime.h>
#include <cuda_bf16.h>
#include <cstdint>

#define UU 200000
#define NN 50000
#define EE 1600000

// Scratch (static __device__ arrays; allocation APIs are forbidden)
__device__ float g_P[(size_t)UU * 64];   // u2e @ W1[:64]
__device__ float g_Q[(size_t)NN * 64];   // u2e[nodes] @ W1[64:] + b1
__device__ float g_ex[EE];               // exp(logit) per edge
// Weights (bf16) pre-packed in m16n8k16 B-fragment order.
// word[(nt*32 + lane)*8 + ks*2 + reg] (reg0: k=ks*16+tg*2, reg1: +8)
__device__ uint32_t g_W2f[2048];
__device__ uint32_t g_W1tf[2048];  // W1 rows 0..63
__device__ uint32_t g_W1bf[2048];  // W1 rows 64..127

// ================= helpers =================
__device__ __forceinline__ unsigned short f2bf(float x) {
    __nv_bfloat16 b = __float2bfloat16_rn(x);
    return *reinterpret_cast<unsigned short*>(&b);
}
// pack pair (a,b) to bf16x2 word (a in low half)
__device__ __forceinline__ uint32_t cvt2(float a, float b) {
    uint32_t r;
    asm("cvt.rn.bf16x2.f32 %0, %1, %2;" : "=r"(r) : "f"(b), "f"(a));
    return r;
}

// D(16x8,f32) += A(16x16,bf16,row) x B(16x8,bf16,col)
__device__ __forceinline__ void mma_bf16(float (&c)[4],
    uint32_t a0, uint32_t a1, uint32_t a2, uint32_t a3,
    uint32_t b0, uint32_t b1)
{
    asm volatile(
        "mma.sync.aligned.m16n8k16.row.col.f32.bf16.bf16.f32 "
        "{%0,%1,%2,%3}, {%4,%5,%6,%7}, {%8,%9}, {%0,%1,%2,%3};"
        : "+f"(c[0]), "+f"(c[1]), "+f"(c[2]), "+f"(c[3])
        : "r"(a0), "r"(a1), "r"(a2), "r"(a3), "r"(b0), "r"(b1));
}

// 4 MMAs for one n-tile (K=64, single product)
__device__ __forceinline__ void mma_1p_ntile(float (&acc)[4],
    const uint32_t (&a)[4][4], const uint32_t* __restrict__ Bf, int nt, int lane)
{
    const uint4* B = (const uint4*)(Bf + (nt * 32 + lane) * 8);
    uint4 b0 = __ldg(B), b1 = __ldg(B + 1);
    mma_bf16(acc, a[0][0], a[0][1], a[0][2], a[0][3], b0.x, b0.y);
    mma_bf16(acc, a[1][0], a[1][1], a[1][2], a[1][3], b0.z, b0.w);
    mma_bf16(acc, a[2][0], a[2][1], a[2][2], a[2][3], b1.x, b1.y);
    mma_bf16(acc, a[3][0], a[3][1], a[3][2], a[3][3], b1.z, b1.w);
}

// Load per-warp A fragments from pitch-36 smem tile
__device__ __forceinline__ void load_afrag(
    const uint32_t* __restrict__ sH, int rb, int g, int tg, uint32_t (&a)[4][4])
{
#pragma unroll
    for (int ks = 0; ks < 4; ks++) {
        int b0 = (rb + g) * 36 + ks * 8 + tg;
        int b1 = b0 + 8 * 36;
        a[ks][0] = sH[b0];     a[ks][1] = sH[b1];
        a[ks][2] = sH[b0 + 4]; a[ks][3] = sH[b1 + 4];
    }
}

// ============================================================
// prep_pack: pack a 64x64 k-major weight block into bf16 B-fragment order.
// ============================================================
__global__ void prep_pack(const float* __restrict__ W, uint32_t* __restrict__ dst)
{
    int i = blockIdx.x * blockDim.x + threadIdx.x;
    if (i >= 2048) return;
    int nt = i >> 8, L = (i >> 3) & 31, w = i & 7;
    int ks = w >> 1, reg = w & 1;
    int g = L >> 2, tg = L & 3;
    int n = nt * 8 + g;
    int k = ks * 16 + reg * 8 + tg * 2;
    float v0 = __ldg(W + k * 64 + n);
    float v1 = __ldg(W + (k + 1) * 64 + n);
    dst[i] = (uint32_t)f2bf(v0) | ((uint32_t)f2bf(v1) << 16);
}

// ============================================================
// rowgemm_mma: out[r] = src[gather?gth[r]:r] @ W(64x64) (+ bias)  via HMMA
// 256 threads = 8 warps; 128 rows/block.
// ============================================================
template <bool GATHER, bool BIAS>
__global__ void __launch_bounds__(256) rowgemm_mma(
    const float* __restrict__ src, const int* __restrict__ gth,
    const uint32_t* __restrict__ Bf, const float* __restrict__ bias,
    float* __restrict__ out, int rows)
{
    __shared__ uint32_t sH[128 * 36];

    int tid = threadIdx.x;
    int wid = tid >> 5, lane = tid & 31;
    int g = lane >> 2, tg = lane & 3;
    int r0 = blockIdx.x * 128;

    // load + convert; each iter covers one row's 8-k chunk
    for (int i = tid; i < 1024; i += 256) {
        int r = i >> 3, k8 = i & 7;
        int gr = r0 + r;
        float4 p0 = make_float4(0.f, 0.f, 0.f, 0.f), p1 = p0;
        if (gr < rows) {
            long s = GATHER ? (long)__ldg(gth + gr) : (long)gr;
            const float4* Pr = (const float4*)(src + s * 64) + k8 * 2;
            p0 = __ldg(Pr); p1 = __ldg(Pr + 1);
        }
        *(uint4*)(sH + r * 36 + k8 * 4) = make_uint4(
            cvt2(p0.x, p0.y), cvt2(p0.z, p0.w),
            cvt2(p1.x, p1.y), cvt2(p1.z, p1.w));
    }
    __syncthreads();

    int rb = wid * 16;
    uint32_t a[4][4];
    load_afrag(sH, rb, g, tg, a);

#pragma unroll
    for (int nt = 0; nt < 8; nt++) {
        float acc[4] = {0.f, 0.f, 0.f, 0.f};
        mma_1p_ntile(acc, a, Bf, nt, lane);
        int c0 = nt * 8 + tg * 2;
        float a0 = 0.f, a1 = 0.f;
        if (BIAS) { a0 = __ldg(bias + c0); a1 = __ldg(bias + c0 + 1); }
        int row0 = r0 + rb + g, row1 = row0 + 8;
        if (row0 < rows)
            *(float2*)(out + (size_t)row0 * 64 + c0) = make_float2(acc[0] + a0, acc[1] + a1);
        if (row1 < rows)
            *(float2*)(out + (size_t)row1 * 64 + c0) = make_float2(acc[2] + a0, acc[3] + a1);
    }
}

// ============================================================
// edge_mlp_mma: per 128-edge tile
//   h = relu(P[nb]+Q[sg]) -> bf16 tile in smem (pitch 36 words/row)
//   D = h @ W2 via mma.sync (HMMA), fp32 accum
//   epilogue: relu(D+b2).w3, 4-lane reduce, exp -> g_ex
// ============================================================
__global__ void __launch_bounds__(256) edge_mlp_mma(
    const int* __restrict__ neigh, const int* __restrict__ seg,
    const float* __restrict__ b2, const float* __restrict__ w3,
    const float* __restrict__ b3)
{
    __shared__ uint32_t sH[128 * 36];
    __shared__ int sIdx[256];

    int tid = threadIdx.x;
    int wid = tid >> 5, lane = tid & 31;
    int g = lane >> 2, tg = lane & 3;
    int e0 = blockIdx.x * 128;

    if (tid < 128) {
        sIdx[tid]       = __ldg(neigh + e0 + tid);
        sIdx[128 + tid] = __ldg(seg   + e0 + tid);
    }
    __syncthreads();

    for (int i = tid; i < 1024; i += 256) {
        int r = i >> 3, k8 = i & 7;
        const float4* Pr = (const float4*)(g_P + (size_t)sIdx[r] * 64) + k8 * 2;
        const float4* Qr = (const float4*)(g_Q + (size_t)sIdx[128 + r] * 64) + k8 * 2;
        float4 p0 = __ldg(Pr), p1 = __ldg(Pr + 1);
        float4 q0 = __ldg(Qr), q1 = __ldg(Qr + 1);
        *(uint4*)(sH + r * 36 + k8 * 4) = make_uint4(
            cvt2(fmaxf(p0.x + q0.x, 0.f), fmaxf(p0.y + q0.y, 0.f)),
            cvt2(fmaxf(p0.z + q0.z, 0.f), fmaxf(p0.w + q0.w, 0.f)),
            cvt2(fmaxf(p1.x + q1.x, 0.f), fmaxf(p1.y + q1.y, 0.f)),
            cvt2(fmaxf(p1.z + q1.z, 0.f), fmaxf(p1.w + q1.w, 0.f)));
    }
    __syncthreads();

    int rb = wid * 16;
    uint32_t a[4][4];
    load_afrag(sH, rb, g, tg, a);

    float s0 = 0.f, s1 = 0.f;
#pragma unroll
    for (int nt = 0; nt < 8; nt++) {
        float acc[4] = {0.f, 0.f, 0.f, 0.f};
        mma_1p_ntile(acc, a, g_W2f, nt, lane);
        int c0 = nt * 8 + tg * 2, c1 = c0 + 1;
        float bb0 = __ldg(b2 + c0), bb1 = __ldg(b2 + c1);
        float ww0 = __ldg(w3 + c0), ww1 = __ldg(w3 + c1);
        s0 += fmaxf(acc[0] + bb0, 0.f) * ww0 + fmaxf(acc[1] + bb1, 0.f) * ww1;
        s1 += fmaxf(acc[2] + bb0, 0.f) * ww0 + fmaxf(acc[3] + bb1, 0.f) * ww1;
    }
    s0 += __shfl_xor_sync(0xffffffffu, s0, 1);
    s0 += __shfl_xor_sync(0xffffffffu, s0, 2);
    s1 += __shfl_xor_sync(0xffffffffu, s1, 1);
    s1 += __shfl_xor_sync(0xffffffffu, s1, 2);
    if (tg == 0) {
        float b3v = __ldg(b3);
        g_ex[e0 + rb + g]     = expf(s0 + b3v);
        g_ex[e0 + rb + g + 8] = expf(s1 + b3v);
    }
}

// ============================================================
// agg: one warp per node — inline rowptr binary search, softmax denom,
// weighted neighbor sum; half-warp float4 lanes, 4 edges in flight.
// ============================================================
__global__ void __launch_bounds__(256) agg_k(
    const int* __restrict__ nodes, const int* __restrict__ neigh,
    const int* __restrict__ seg, const float* __restrict__ u2e,
    float* __restrict__ out)
{
    int w = (blockIdx.x * 256 + threadIdx.x) >> 5;
    int lane = threadIdx.x & 31;
    if (w >= NN) return;
    int half = lane >> 4, l16 = lane & 15;

    // inline lower_bound: lanes 0-15 search w, lanes 16-31 search w+1
    int target = w + half;
    int lo = 0, hi = EE;
    while (lo < hi) {
        int mid = (lo + hi) >> 1;
        if (__ldg(seg + mid) < target) lo = mid + 1; else hi = mid;
    }
    int s = __shfl_sync(0xffffffffu, lo, 0);
    int t = __shfl_sync(0xffffffffu, lo, 16);

    if (s == t) {  // no neighbors: own embedding
        int u = __ldg(nodes + w);
        if (half == 0) {
            float4 v = __ldg((const float4*)(u2e + (size_t)u * 64) + l16);
            *((float4*)(out + (size_t)w * 64) + l16) = v;
        }
        return;
    }

    float d = 0.f;
    for (int e = s + lane; e < t; e += 32) d += __ldg(g_ex + e);
#pragma unroll
    for (int m = 16; m; m >>= 1) d += __shfl_xor_sync(0xffffffffu, d, m);
    float inv = 1.f / d;

    // 4 edges in flight per half-warp; dual accumulators
    float4 a = make_float4(0.f, 0.f, 0.f, 0.f);
    float4 b = make_float4(0.f, 0.f, 0.f, 0.f);
    int e = s;
    for (; e + 8 <= t; e += 8) {
        int   ea = e + half,     eb = e + 2 + half;
        int   ec = e + 4 + half, ed = e + 6 + half;
        int   na = __ldg(neigh + ea), nb = __ldg(neigh + eb);
        int   nc = __ldg(neigh + ec), nd = __ldg(neigh + ed);
        float wa = __ldg(g_ex + ea), wb = __ldg(g_ex + eb);
        float wc = __ldg(g_ex + ec), wd = __ldg(g_ex + ed);
        float4 va = __ldg((const float4*)(u2e + (size_t)na * 64) + l16);
        float4 vb = __ldg((const float4*)(u2e + (size_t)nb * 64) + l16);
        float4 vc = __ldg((const float4*)(u2e + (size_t)nc * 64) + l16);
        float4 vd = __ldg((const float4*)(u2e + (size_t)nd * 64) + l16);
        a.x = fmaf(wa, va.x, fmaf(wb, vb.x, a.x));
        a.y = fmaf(wa, va.y, fmaf(wb, vb.y, a.y));
        a.z = fmaf(wa, va.z, fmaf(wb, vb.z, a.z));
        a.w = fmaf(wa, va.w, fmaf(wb, vb.w, a.w));
        b.x = fmaf(wc, vc.x, fmaf(wd, vd.x, b.x));
        b.y = fmaf(wc, vc.y, fmaf(wd, vd.y, b.y));
        b.z = fmaf(wc, vc.z, fmaf(wd, vd.z, b.z));
        b.w = fmaf(wc, vc.w, fmaf(wd, vd.w, b.w));
    }
    for (; e < t; e += 2) {
        int ee = e + half;
        if (ee < t) {
            int   n0 = __ldg(neigh + ee);
            float w0 = __ldg(g_ex + ee);
            float4 v = __ldg((const float4*)(u2e + (size_t)n0 * 64) + l16);
            a.x = fmaf(w0, v.x, a.x); a.y = fmaf(w0, v.y, a.y);
            a.z = fmaf(w0, v.z, a.z); a.w = fmaf(w0, v.w, a.w);
        }
    }
    a.x += b.x; a.y += b.y; a.z += b.z; a.w += b.w;
    a.x += __shfl_xor_sync(0xffffffffu, a.x, 16);
    a.y += __shfl_xor_sync(0xffffffffu, a.y, 16);
    a.z += __shfl_xor_sync(0xffffffffu, a.z, 16);
    a.w += __shfl_xor_sync(0xffffffffu, a.w, 16);
    if (half == 0) {
        a.x *= inv; a.y *= inv; a.z *= inv; a.w *= inv;
        *((float4*)(out + (size_t)w * 64) + l16) = a;
    }
}

// ============================================================
extern "C" void kernel_launch(void* const* d_in, const int* in_sizes, int n_in,
                              void* d_out, int out_size)
{
    const int*   nodes = (const int*)d_in[0];
    const int*   neigh = (const int*)d_in[1];
    const int*   seg   = (const int*)d_in[2];
    const float* u2e   = (const float*)d_in[3];
    const float* W1    = (const float*)d_in[4];
    const float* b1    = (const float*)d_in[5];
    const float* W2    = (const float*)d_in[6];
    const float* b2    = (const float*)d_in[7];
    const float* w3    = (const float*)d_in[8];
    const float* b3    = (const float*)d_in[9];
    float* out = (float*)d_out;

    float *dP, *dQ;
    cudaGetSymbolAddress((void**)&dP, g_P);
    cudaGetSymbolAddress((void**)&dQ, g_Q);
    uint32_t *pW2, *pW1t, *pW1b;
    cudaGetSymbolAddress((void**)&pW2,  g_W2f);
    cudaGetSymbolAddress((void**)&pW1t, g_W1tf);
    cudaGetSymbolAddress((void**)&pW1b, g_W1bf);

    // weight packs (bf16, fragment order)
    prep_pack<<<8, 256>>>(W2, pW2);
    prep_pack<<<8, 256>>>(W1, pW1t);
    prep_pack<<<8, 256>>>(W1 + 64 * 64, pW1b);
    // P = u2e @ W1[:64]
    rowgemm_mma<false, false><<<(UU + 127) / 128, 256>>>(
        u2e, nullptr, pW1t, nullptr, dP, UU);
    // Q = u2e[nodes] @ W1[64:] + b1
    rowgemm_mma<true, true><<<(NN + 127) / 128, 256>>>(
        u2e, nodes, pW1b, b1, dQ, NN);
    // per-edge MLP -> exp(logit)  (HMMA)
    edge_mlp_mma<<<EE / 128, 256>>>(neigh, seg, b2, w3, b3);
    // segment softmax + weighted aggregation (+ zero-neighbor fallback)
    agg_k<<<(NN * 32 + 255) / 256, 256>>>(nodes, neigh, seg, u2e, out);
}